// round 1
// baseline (speedup 1.0000x reference)
#include <cuda_runtime.h>

#define B  128
#define C  49
#define NN 3136   // tokens = 56*56

typedef unsigned long long u64;

// ---------------- scratch (device globals; no allocation) ----------------
__device__ float    g_v[B*NN];        // mean over channels      (1.6 MB)
__device__ float    g_q[B*C*C];       // q conv output q[b][o][p]
__device__ float    g_qw[B*C*C];      // qw[b][c][i] = sum_j q[b,c,j]*Wsr[j,i]
__device__ float    g_qb[B*C];        // qb[b][c]    = sum_j q[b,c,j]*bsr[j]
__device__ unsigned g_amax[B*C];      // order-encoded fp32 max (atomicMax)
__device__ float    g_spart[14*B*NN]; // k-split partials of s = v @ Wproj^T

// ---------------- helpers ----------------
__device__ __forceinline__ void fma2(u64 &d, u64 a, u64 b) {
    asm("fma.rn.f32x2 %0, %1, %2, %0;" : "+l"(d) : "l"(a), "l"(b));
}
__device__ __forceinline__ float f2lo(u64 v){ return __uint_as_float((unsigned)v); }
__device__ __forceinline__ float f2hi(u64 v){ return __uint_as_float((unsigned)(v>>32)); }

// monotone fp32 <-> uint encoding for atomicMax
__device__ __forceinline__ unsigned fenc(float f){
    unsigned u = __float_as_uint(f);
    return (u & 0x80000000u) ? ~u : (u | 0x80000000u);
}
__device__ __forceinline__ float fdec(unsigned e){
    return (e & 0x80000000u) ? __uint_as_float(e & 0x7FFFFFFFu)
                             : __uint_as_float(~e);
}

// ---------------- kernels ----------------

__global__ void k_init(){
    int i = blockIdx.x*256 + threadIdx.x;
    if (i < B*C) g_amax[i] = 0u;   // below enc(-inf)=0x007FFFFF
}

// v[b,n] = mean_c x[b,c,n]
__global__ void k_v(const float* __restrict__ x){
    int n = blockIdx.x*256 + threadIdx.x;
    int b = blockIdx.y;
    if (n >= NN) return;
    const float* xp = x + (size_t)b*C*NN + n;
    float s = 0.f;
    #pragma unroll
    for (int c = 0; c < C; c++) s += xp[c*NN];
    g_v[b*NN + n] = s * (1.0f/49.0f);
}

// q[b,o,p] = Conv2d(x, Wq, k=8, stride=8).  Per block: one batch b.
// k-loop over input channel i; stage plane x[b,i,:,:] (12.5KB) + Wq[:,i,:,:] (12.5KB).
__global__ void __launch_bounds__(256) k_qconv(const float* __restrict__ x,
                                               const float* __restrict__ Wq){
    __shared__ __align__(16) float sp[NN];     // one channel plane, 56x56
    __shared__ __align__(16) float sw[C*64];   // Wq[o][i fixed][kh][kw]
    const int b = blockIdx.x, tid = threadIdx.x;
    const int g = tid >> 5, lane = tid & 31;   // warp-group g picks o-set
    const int no = (g == 0) ? 7 : 6;           // o = g + 8*t
    const int np = (lane < 17) ? 2 : 1;        // p = lane (+32)

    u64 acc[7][2];
    #pragma unroll
    for (int t = 0; t < 7; t++){ acc[t][0] = 0ull; acc[t][1] = 0ull; }

    const u64* sp2 = (const u64*)sp;
    const u64* sw2 = (const u64*)sw;

    const int ph0 = lane / 7,        pw0 = lane % 7;
    const int ph1 = (lane + 32) / 7, pw1 = (lane + 32) % 7;

    for (int i = 0; i < C; i++){
        for (int idx = tid; idx < NN; idx += 256)
            sp[idx] = x[((size_t)b*C + i)*NN + idx];
        for (int idx = tid; idx < NN; idx += 256){
            int o = idx >> 6, t = idx & 63;
            sw[idx] = Wq[o*3136 + i*64 + t];
        }
        __syncthreads();

        #pragma unroll
        for (int kh = 0; kh < 8; kh++){
            u64 pl0[4], pl1[4];
            {
                int base = ((ph0*8 + kh)*28) + pw0*4;   // u64 index into plane
                pl0[0]=sp2[base]; pl0[1]=sp2[base+1]; pl0[2]=sp2[base+2]; pl0[3]=sp2[base+3];
            }
            if (np == 2){
                int base = ((ph1*8 + kh)*28) + pw1*4;
                pl1[0]=sp2[base]; pl1[1]=sp2[base+1]; pl1[2]=sp2[base+2]; pl1[3]=sp2[base+3];
            }
            for (int t = 0; t < no; t++){
                int o = g + 8*t;
                int wbase = o*32 + kh*4;
                u64 w0=sw2[wbase], w1=sw2[wbase+1], w2v=sw2[wbase+2], w3=sw2[wbase+3];
                fma2(acc[t][0], w0, pl0[0]); fma2(acc[t][0], w1,  pl0[1]);
                fma2(acc[t][0], w2v,pl0[2]); fma2(acc[t][0], w3,  pl0[3]);
                if (np == 2){
                    fma2(acc[t][1], w0, pl1[0]); fma2(acc[t][1], w1,  pl1[1]);
                    fma2(acc[t][1], w2v,pl1[2]); fma2(acc[t][1], w3,  pl1[3]);
                }
            }
        }
        __syncthreads();
    }
    for (int t = 0; t < no; t++){
        int o = g + 8*t;
        g_q[((size_t)b*C + o)*C + lane] = f2lo(acc[t][0]) + f2hi(acc[t][0]);
        if (np == 2)
            g_q[((size_t)b*C + o)*C + lane + 32] = f2lo(acc[t][1]) + f2hi(acc[t][1]);
    }
}

// qw[b,c,i] = sum_j q[b,c,j] * Wsr[j,i];  qb[b,c] = sum_j q[b,c,j] * bsr[j]
__global__ void k_qw(const float* __restrict__ Wsr, const float* __restrict__ bsr){
    __shared__ float sq[C*C], swr[C*C], sb[C];
    const int b = blockIdx.x, tid = threadIdx.x;
    for (int idx = tid; idx < C*C; idx += 256){
        sq[idx]  = g_q[(size_t)b*C*C + idx];
        swr[idx] = Wsr[idx];
    }
    if (tid < C) sb[tid] = bsr[tid];
    __syncthreads();
    for (int idx = tid; idx < C*C; idx += 256){
        int c = idx / C, i = idx % C;
        float s = 0.f;
        #pragma unroll
        for (int j = 0; j < C; j++) s += sq[c*C + j] * swr[j*C + i];
        g_qw[(size_t)b*C*C + idx] = s;
    }
    if (tid < C){
        float s = 0.f;
        #pragma unroll
        for (int j = 0; j < C; j++) s += sq[tid*C + j] * sb[j];
        g_qb[b*C + tid] = s;
    }
}

// amax[b,c] = max_n sum_i qw[b,c,i] * x[b,i,n]   (n-chunks of 112, f32x2 over n)
__global__ void __launch_bounds__(224) k_amax(const float* __restrict__ x){
    __shared__ __align__(16) float xs[C*112];     // x tile [i][nn]
    __shared__ __align__(16) float qd[C*C*2];     // qw duplicated pairs
    __shared__ unsigned samax[C];
    const int b = blockIdx.y, n0 = blockIdx.x*112, tid = threadIdx.x;

    for (int idx = tid; idx < C*112; idx += 224){
        int i = idx/112, nn = idx%112;
        xs[idx] = x[((size_t)b*C + i)*NN + n0 + nn];
    }
    for (int idx = tid; idx < C*C; idx += 224){
        float w = g_qw[(size_t)b*C*C + idx];
        qd[2*idx] = w; qd[2*idx+1] = w;
    }
    if (tid < C) samax[tid] = 0u;
    __syncthreads();

    const int np = tid % 56, g = tid / 56;   // g in 0..3 ; c = g + 4*t
    const int nc = (g == 0) ? 13 : 12;
    u64 acc[13];
    #pragma unroll
    for (int t = 0; t < 13; t++) acc[t] = 0ull;

    const u64* xs2 = (const u64*)xs;
    const u64* qd2 = (const u64*)qd;
    for (int i = 0; i < C; i++){
        u64 x2 = xs2[i*56 + np];
        #pragma unroll
        for (int t = 0; t < 13; t++){
            if (t < nc){
                int c = g + 4*t;
                fma2(acc[t], qd2[c*C + i], x2);
            }
        }
    }
    for (int t = 0; t < nc; t++){
        int c = g + 4*t;
        float m = fmaxf(f2lo(acc[t]), f2hi(acc[t]));
        atomicMax(&samax[c], fenc(m));
    }
    __syncthreads();
    if (tid < C) atomicMax(&g_amax[b*C + tid], samax[tid]);
}

// s = v @ Wproj^T : s[b,m] = sum_n Wproj[m,n]*v[b,n].  M=128(all b) x Ntile=112, K split 14.
__global__ void __launch_bounds__(512) k_sgemm(const float* __restrict__ Wp){
    __shared__ __align__(16) float va[128*34];   // v tile  [b][k] (pad 34)
    __shared__ __align__(16) float wb[112*34];   // Wp tile [m][k] (pad 34)
    const int m0 = blockIdx.x*112;
    const int kb = blockIdx.y*224;
    const int tid = threadIdx.x;
    const int tb = tid >> 4;      // 0..31 -> 4 b's each
    const int tm = tid & 15;      // 0..15 -> 7 m's each

    u64 acc[4][7];
    #pragma unroll
    for (int j = 0; j < 4; j++)
        #pragma unroll
        for (int q = 0; q < 7; q++) acc[j][q] = 0ull;

    for (int kk = 0; kk < 224; kk += 32){
        __syncthreads();
        for (int idx = tid; idx < 128*32; idx += 512){
            int bb = idx >> 5, k = idx & 31;
            va[bb*34 + k] = g_v[bb*NN + kb + kk + k];
        }
        for (int idx = tid; idx < 112*32; idx += 512){
            int m = idx >> 5, k = idx & 31;
            wb[m*34 + k] = Wp[(size_t)(m0 + m)*NN + kb + kk + k];
        }
        __syncthreads();
        #pragma unroll
        for (int kp = 0; kp < 16; kp++){
            u64 a0 = *(const u64*)&va[(tb*4 + 0)*34 + 2*kp];
            u64 a1 = *(const u64*)&va[(tb*4 + 1)*34 + 2*kp];
            u64 a2 = *(const u64*)&va[(tb*4 + 2)*34 + 2*kp];
            u64 a3 = *(const u64*)&va[(tb*4 + 3)*34 + 2*kp];
            #pragma unroll
            for (int q = 0; q < 7; q++){
                u64 w = *(const u64*)&wb[(tm*7 + q)*34 + 2*kp];
                fma2(acc[0][q], a0, w);
                fma2(acc[1][q], a1, w);
                fma2(acc[2][q], a2, w);
                fma2(acc[3][q], a3, w);
            }
        }
    }
    const int pc = blockIdx.y;
    #pragma unroll
    for (int j = 0; j < 4; j++)
        #pragma unroll
        for (int q = 0; q < 7; q++){
            int bb = tb*4 + j, m = m0 + tm*7 + q;
            g_spart[((size_t)pc*B + bb)*NN + m] = f2lo(acc[j][q]) + f2hi(acc[j][q]);
        }
}

// y[b,m,c] = (amax[b,c]+qb[b,c]) * s[b,m]   (sum the 14 k-split partials here)
__global__ void k_final(float* __restrict__ out){
    __shared__ float ss[64];
    __shared__ float sam[C];
    const int b = blockIdx.y, m0 = blockIdx.x*64, tid = threadIdx.x;
    if (tid < 64){
        float s = 0.f;
        #pragma unroll
        for (int p = 0; p < 14; p++) s += g_spart[((size_t)p*B + b)*NN + m0 + tid];
        ss[tid] = s;
    }
    if (tid >= 64 && tid < 64 + C){
        int c = tid - 64;
        sam[c] = fdec(g_amax[b*C + c]) + g_qb[b*C + c];
    }
    __syncthreads();
    float* ob = out + ((size_t)b*NN + m0)*C;
    for (int idx = tid; idx < 64*C; idx += 256){
        int mi = idx / C, c = idx % C;
        ob[idx] = sam[c] * ss[mi];
    }
}

// ---------------- launch ----------------
extern "C" void kernel_launch(void* const* d_in, const int* in_sizes, int n_in,
                              void* d_out, int out_size){
    const float* x    = (const float*)d_in[0];
    const float* Wq   = (const float*)d_in[1];
    const float* Wsr  = (const float*)d_in[2];
    const float* bsr  = (const float*)d_in[3];
    const float* Wp   = (const float*)d_in[4];
    float* out = (float*)d_out;

    k_init <<< (B*C + 255)/256, 256 >>> ();
    k_v    <<< dim3((NN + 255)/256, B), 256 >>> (x);
    k_qconv<<< B, 256 >>> (x, Wq);
    k_qw   <<< B, 256 >>> (Wsr, bsr);
    k_amax <<< dim3(28, B), 224 >>> (x);
    k_sgemm<<< dim3(28, 14), 512 >>> (Wp);
    k_final<<< dim3(49, B), 256 >>> (out);
}

// round 2
// speedup vs baseline: 1.2223x; 1.2223x over previous
#include <cuda_runtime.h>

#define B  128
#define C  49
#define NN 3136   // tokens = 56*56

typedef unsigned long long u64;

// ---------------- scratch (device globals; no allocation) ----------------
__device__ float    g_v[B*NN];        // mean over channels
__device__ float    g_qw[B*C*C];      // qw[b][c][i] = sum_j q[b,c,j]*Wsr[j,i]
__device__ float    g_qb[B*C];        // qb[b][c]    = sum_j q[b,c,j]*bsr[j]
__device__ unsigned g_amax[B*C];      // order-encoded fp32 max
__device__ float    g_spart[14*B*NN]; // k-split partials of s = v @ Wproj^T

// ---------------- helpers ----------------
__device__ __forceinline__ void fma2(u64 &d, u64 a, u64 b) {
    asm("fma.rn.f32x2 %0, %1, %2, %0;" : "+l"(d) : "l"(a), "l"(b));
}
__device__ __forceinline__ float f2lo(u64 v){ return __uint_as_float((unsigned)v); }
__device__ __forceinline__ float f2hi(u64 v){ return __uint_as_float((unsigned)(v>>32)); }

__device__ __forceinline__ unsigned fenc(float f){
    unsigned u = __float_as_uint(f);
    return (u & 0x80000000u) ? ~u : (u | 0x80000000u);
}
__device__ __forceinline__ float fdec(unsigned e){
    return (e & 0x80000000u) ? __uint_as_float(e & 0x7FFFFFFFu)
                             : __uint_as_float(~e);
}

__device__ __forceinline__ void cpa16(float* s, const float* g){
    unsigned ss = (unsigned)__cvta_generic_to_shared(s);
    asm volatile("cp.async.cg.shared.global [%0], [%1], 16;" :: "r"(ss), "l"(g));
}
__device__ __forceinline__ void cpa_commit(){
    asm volatile("cp.async.commit_group;");
}
template<int N>
__device__ __forceinline__ void cpa_wait(){
    asm volatile("cp.async.wait_group %0;" :: "n"(N));
}

// ---------------- kernels ----------------

__global__ void k_init(){
    int i = blockIdx.x*256 + threadIdx.x;
    if (i < B*C) g_amax[i] = 0u;
}

// Fused: q = Conv2d(x,Wq,8,str8)  ->  qw = q @ Wsr,  qb = q @ bsr.
// One block per batch. Double-buffered cp.async staging of (plane, weights).
__global__ void __launch_bounds__(256) k_qconv_qw(const float* __restrict__ x,
                                                  const float* __restrict__ Wq,
                                                  const float* __restrict__ Wsr,
                                                  const float* __restrict__ bsr){
    extern __shared__ __align__(16) float smem[];
    float* planeB[2] = { smem,        smem + 6272 };
    float* wbufB [2] = { smem + 3136, smem + 9408 };
    float* sWsr = smem + 12544;          // 2401 floats
    float* sbsr = smem + 14945;          // 49 floats
    float* sq   = smem;                  // epilogue reuse (2401 <= 3136)

    const int b = blockIdx.x, tid = threadIdx.x;
    const int g = tid >> 5, lane = tid & 31;
    const int no = (g == 0) ? 7 : 6;     // o = g + 8*t
    const int np = (lane < 17) ? 2 : 1;  // p = lane (+32)

    // stage Wsr / bsr (async main part + scalar tail)
    for (int ch = tid; ch < 600; ch += 256) cpa16(sWsr + ch*4, Wsr + ch*4);
    if (tid == 0) sWsr[2400] = Wsr[2400];
    if (tid < C)  sbsr[tid] = bsr[tid];
    cpa_commit();

    // prefetch i = 0
    {
        const float* gp = x + (size_t)b*C*NN;
        for (int ch = tid; ch < 784; ch += 256) cpa16(planeB[0] + ch*4, gp + ch*4);
        for (int ch = tid; ch < 784; ch += 256){
            int o = ch >> 4, t4 = ch & 15;
            cpa16(wbufB[0] + ch*4, Wq + o*3136 + t4*4);
        }
        cpa_commit();
    }

    u64 acc[7][2];
    #pragma unroll
    for (int t = 0; t < 7; t++){ acc[t][0] = 0ull; acc[t][1] = 0ull; }

    const int ph0 = lane / 7,        pw0 = lane % 7;
    const int ph1 = (lane + 32) / 7, pw1 = (lane + 32) % 7;

    for (int i = 0; i < C; i++){
        if (i + 1 < C){
            const float* gp = x + ((size_t)b*C + (i+1))*NN;
            float* pd = planeB[(i+1)&1];
            float* wd = wbufB [(i+1)&1];
            for (int ch = tid; ch < 784; ch += 256) cpa16(pd + ch*4, gp + ch*4);
            for (int ch = tid; ch < 784; ch += 256){
                int o = ch >> 4, t4 = ch & 15;
                cpa16(wd + ch*4, Wq + o*3136 + (i+1)*64 + t4*4);
            }
            cpa_commit();
            cpa_wait<1>();
        } else {
            cpa_wait<0>();
        }
        __syncthreads();

        const u64* sp2 = (const u64*)planeB[i&1];
        const u64* sw2 = (const u64*)wbufB [i&1];

        #pragma unroll
        for (int kh = 0; kh < 8; kh++){
            u64 pl0[4], pl1[4];
            {
                int base = ((ph0*8 + kh)*28) + pw0*4;
                pl0[0]=sp2[base]; pl0[1]=sp2[base+1]; pl0[2]=sp2[base+2]; pl0[3]=sp2[base+3];
            }
            if (np == 2){
                int base = ((ph1*8 + kh)*28) + pw1*4;
                pl1[0]=sp2[base]; pl1[1]=sp2[base+1]; pl1[2]=sp2[base+2]; pl1[3]=sp2[base+3];
            }
            for (int t = 0; t < no; t++){
                int o = g + 8*t;
                int wbase = o*32 + kh*4;
                u64 w0=sw2[wbase], w1=sw2[wbase+1], w2v=sw2[wbase+2], w3=sw2[wbase+3];
                fma2(acc[t][0], w0, pl0[0]); fma2(acc[t][0], w1,  pl0[1]);
                fma2(acc[t][0], w2v,pl0[2]); fma2(acc[t][0], w3,  pl0[3]);
                if (np == 2){
                    fma2(acc[t][1], w0, pl1[0]); fma2(acc[t][1], w1,  pl1[1]);
                    fma2(acc[t][1], w2v,pl1[2]); fma2(acc[t][1], w3,  pl1[3]);
                }
            }
        }
        __syncthreads();
    }

    // ---- epilogue: q -> smem, then qw = q@Wsr, qb = q@bsr (in-block) ----
    for (int t = 0; t < no; t++){
        int o = g + 8*t;
        sq[o*C + lane] = f2lo(acc[t][0]) + f2hi(acc[t][0]);
        if (np == 2)
            sq[o*C + lane + 32] = f2lo(acc[t][1]) + f2hi(acc[t][1]);
    }
    __syncthreads();

    for (int idx = tid; idx < C*C; idx += 256){
        int c = idx / C, i2 = idx % C;
        float s = 0.f;
        #pragma unroll
        for (int j = 0; j < C; j++) s += sq[c*C + j] * sWsr[j*C + i2];
        g_qw[(size_t)b*C*C + idx] = s;
    }
    if (tid < C){
        float s = 0.f;
        #pragma unroll
        for (int j = 0; j < C; j++) s += sq[tid*C + j] * sbsr[j];
        g_qb[b*C + tid] = s;
    }
}

// Fused: v[b,n] = mean_c x[b,c,n]  AND  amax[b,c] = max_n sum_i qw[b,c,i]*x[b,i,n]
// grid (28 n-tiles of 112, B). 224 threads: 8 c-groups x 28 n-quads.
__global__ void __launch_bounds__(224) k_amax_v(const float* __restrict__ x){
    __shared__ __align__(16) float xs[C*112];   // [i][nn]
    __shared__ __align__(16) float qd[C*C*2];   // duplicated weight pairs
    __shared__ unsigned samax[C];
    const int b = blockIdx.y, n0 = blockIdx.x*112, tid = threadIdx.x;

    for (int idx = tid; idx < C*112; idx += 224){
        int i = idx/112, nn = idx%112;
        xs[idx] = x[((size_t)b*C + i)*NN + n0 + nn];
    }
    for (int idx = tid; idx < C*C; idx += 224){
        float w = g_qw[(size_t)b*C*C + idx];
        qd[2*idx] = w; qd[2*idx+1] = w;
    }
    if (tid < C) samax[tid] = 0u;
    __syncthreads();

    // channel mean -> v
    if (tid < 112){
        float s = 0.f;
        #pragma unroll
        for (int i = 0; i < C; i++) s += xs[i*112 + tid];
        g_v[b*NN + n0 + tid] = s * (1.0f/49.0f);
    }

    const int cg = tid / 28, nq = tid % 28;   // c = cg*7 + t (masked >= 49)
    u64 acc[7][2];
    #pragma unroll
    for (int t = 0; t < 7; t++){ acc[t][0] = 0ull; acc[t][1] = 0ull; }

    const u64* qd2 = (const u64*)qd;
    const ulonglong2* xs4 = (const ulonglong2*)xs;
    for (int i = 0; i < C; i++){
        ulonglong2 xv = xs4[i*28 + nq];
        #pragma unroll
        for (int t = 0; t < 7; t++){
            int c = cg*7 + t;
            if (c < C){
                u64 w = qd2[c*C + i];
                fma2(acc[t][0], w, xv.x);
                fma2(acc[t][1], w, xv.y);
            }
        }
    }
    #pragma unroll
    for (int t = 0; t < 7; t++){
        int c = cg*7 + t;
        if (c < C){
            float m = fmaxf(fmaxf(f2lo(acc[t][0]), f2hi(acc[t][0])),
                            fmaxf(f2lo(acc[t][1]), f2hi(acc[t][1])));
            atomicMax(&samax[c], fenc(m));
        }
    }
    __syncthreads();
    if (tid < C) atomicMax(&g_amax[b*C + tid], samax[tid]);
}

// s = v @ Wproj^T : s[b,m] = sum_n Wproj[m,n]*v[b,n].
__global__ void __launch_bounds__(512) k_sgemm(const float* __restrict__ Wp){
    __shared__ __align__(16) float va[128*34];
    __shared__ __align__(16) float wb[112*34];
    const int m0 = blockIdx.x*112;
    const int kb = blockIdx.y*224;
    const int tid = threadIdx.x;
    const int tb = tid >> 4;
    const int tm = tid & 15;

    u64 acc[4][7];
    #pragma unroll
    for (int j = 0; j < 4; j++)
        #pragma unroll
        for (int q = 0; q < 7; q++) acc[j][q] = 0ull;

    for (int kk = 0; kk < 224; kk += 32){
        __syncthreads();
        for (int idx = tid; idx < 128*32; idx += 512){
            int bb = idx >> 5, k = idx & 31;
            va[bb*34 + k] = g_v[bb*NN + kb + kk + k];
        }
        for (int idx = tid; idx < 112*32; idx += 512){
            int m = idx >> 5, k = idx & 31;
            wb[m*34 + k] = Wp[(size_t)(m0 + m)*NN + kb + kk + k];
        }
        __syncthreads();
        #pragma unroll
        for (int kp = 0; kp < 16; kp++){
            u64 a0 = *(const u64*)&va[(tb*4 + 0)*34 + 2*kp];
            u64 a1 = *(const u64*)&va[(tb*4 + 1)*34 + 2*kp];
            u64 a2 = *(const u64*)&va[(tb*4 + 2)*34 + 2*kp];
            u64 a3 = *(const u64*)&va[(tb*4 + 3)*34 + 2*kp];
            #pragma unroll
            for (int q = 0; q < 7; q++){
                u64 w = *(const u64*)&wb[(tm*7 + q)*34 + 2*kp];
                fma2(acc[0][q], a0, w);
                fma2(acc[1][q], a1, w);
                fma2(acc[2][q], a2, w);
                fma2(acc[3][q], a3, w);
            }
        }
    }
    const int pc = blockIdx.y;
    #pragma unroll
    for (int j = 0; j < 4; j++)
        #pragma unroll
        for (int q = 0; q < 7; q++){
            int bb = tb*4 + j, m = m0 + tm*7 + q;
            g_spart[((size_t)pc*B + bb)*NN + m] = f2lo(acc[j][q]) + f2hi(acc[j][q]);
        }
}

// y[b,m,c] = (amax[b,c]+qb[b,c]) * s[b,m]
__global__ void k_final(float* __restrict__ out){
    __shared__ float ss[64];
    __shared__ float sam[C];
    const int b = blockIdx.y, m0 = blockIdx.x*64, tid = threadIdx.x;
    if (tid < 64){
        float s = 0.f;
        #pragma unroll
        for (int p = 0; p < 14; p++) s += g_spart[((size_t)p*B + b)*NN + m0 + tid];
        ss[tid] = s;
    }
    if (tid >= 64 && tid < 64 + C){
        int c = tid - 64;
        sam[c] = fdec(g_amax[b*C + c]) + g_qb[b*C + c];
    }
    __syncthreads();
    float* ob = out + ((size_t)b*NN + m0)*C;
    for (int idx = tid; idx < 64*C; idx += 256){
        int mi = idx / C, c = idx % C;
        ob[idx] = sam[c] * ss[mi];
    }
}

// ---------------- launch ----------------
extern "C" void kernel_launch(void* const* d_in, const int* in_sizes, int n_in,
                              void* d_out, int out_size){
    const float* x    = (const float*)d_in[0];
    const float* Wq   = (const float*)d_in[1];
    const float* Wsr  = (const float*)d_in[2];
    const float* bsr  = (const float*)d_in[3];
    const float* Wp   = (const float*)d_in[4];
    float* out = (float*)d_out;

    const int qsmem = (14994) * 4;   // 59976 B dynamic shared
    cudaFuncSetAttribute(k_qconv_qw, cudaFuncAttributeMaxDynamicSharedMemorySize, qsmem);

    k_init     <<< (B*C + 255)/256, 256 >>> ();
    k_qconv_qw <<< B, 256, qsmem >>> (x, Wq, Wsr, bsr);
    k_amax_v   <<< dim3(28, B), 224 >>> (x);
    k_sgemm    <<< dim3(28, 14), 512 >>> (Wp);
    k_final    <<< dim3(49, B), 256 >>> (out);
}

// round 6
// speedup vs baseline: 1.5077x; 1.2334x over previous
#include <cuda_runtime.h>

#define B  128
#define C  49
#define NN 3136   // tokens = 56*56
#define KS 7      // k-splits for s-gemm (3136 = 7*448)

typedef unsigned long long u64;

// ---------------- scratch (device globals; no allocation) ----------------
__device__ float    g_v[B*NN];        // mean over channels
__device__ float    g_qw[B*C*C];      // qw[b][c][i] = sum_j q[b,c,j]*Wsr[j,i]
__device__ float    g_qb[B*C];        // qb[b][c]
__device__ unsigned g_amax[B*C];      // order-encoded fp32 max
__device__ float    g_spart[KS*B*NN]; // k-split partials of s = v @ Wproj^T

// ---------------- helpers ----------------
__device__ __forceinline__ void fma2(u64 &d, u64 a, u64 b) {
    asm("fma.rn.f32x2 %0, %1, %2, %0;" : "+l"(d) : "l"(a), "l"(b));
}
__device__ __forceinline__ float f2lo(u64 v){ return __uint_as_float((unsigned)v); }
__device__ __forceinline__ float f2hi(u64 v){ return __uint_as_float((unsigned)(v>>32)); }

__device__ __forceinline__ unsigned fenc(float f){
    unsigned u = __float_as_uint(f);
    return (u & 0x80000000u) ? ~u : (u | 0x80000000u);
}
__device__ __forceinline__ float fdec(unsigned e){
    return (e & 0x80000000u) ? __uint_as_float(e & 0x7FFFFFFFu)
                             : __uint_as_float(~e);
}

__device__ __forceinline__ void cpa16(float* s, const float* g){
    unsigned ss = (unsigned)__cvta_generic_to_shared(s);
    asm volatile("cp.async.cg.shared.global [%0], [%1], 16;" :: "r"(ss), "l"(g));
}
__device__ __forceinline__ void cpa_commit(){
    asm volatile("cp.async.commit_group;");
}
template<int N>
__device__ __forceinline__ void cpa_wait(){
    asm volatile("cp.async.wait_group %0;" :: "n"(N));
}

// tf32 split helpers
__device__ __forceinline__ unsigned tf32_of(float x){
    unsigned r; asm("cvt.rna.tf32.f32 %0, %1;" : "=r"(r) : "f"(x)); return r;
}
__device__ __forceinline__ void tf32_split(float x, unsigned &hi, unsigned &lo){
    hi = tf32_of(x);
    lo = tf32_of(x - __uint_as_float(hi));
}
__device__ __forceinline__ void mma_tf32(float* d, const unsigned* a, const unsigned* b){
    asm("mma.sync.aligned.m16n8k8.row.col.f32.tf32.tf32.f32 "
        "{%0,%1,%2,%3}, {%4,%5,%6,%7}, {%8,%9}, {%0,%1,%2,%3};"
        : "+f"(d[0]), "+f"(d[1]), "+f"(d[2]), "+f"(d[3])
        : "r"(a[0]), "r"(a[1]), "r"(a[2]), "r"(a[3]), "r"(b[0]), "r"(b[1]));
}

// ---------------- kernels ----------------

__global__ void k_init(){
    int i = blockIdx.x*256 + threadIdx.x;
    if (i < B*C) g_amax[i] = 0u;
}

// Fused: q = Conv2d(x,Wq,8,str8)  ->  qw = q @ Wsr,  qb = q @ bsr.
__global__ void __launch_bounds__(256) k_qconv_qw(const float* __restrict__ x,
                                                  const float* __restrict__ Wq,
                                                  const float* __restrict__ Wsr,
                                                  const float* __restrict__ bsr){
    extern __shared__ __align__(16) float smem[];
    float* planeB[2] = { smem,        smem + 6272 };
    float* wbufB [2] = { smem + 3136, smem + 9408 };
    float* sWsr = smem + 12544;
    float* sbsr = smem + 14945;
    float* sq   = smem;

    const int b = blockIdx.x, tid = threadIdx.x;
    const int g = tid >> 5, lane = tid & 31;
    const int no = (g == 0) ? 7 : 6;
    const int np = (lane < 17) ? 2 : 1;

    for (int ch = tid; ch < 600; ch += 256) cpa16(sWsr + ch*4, Wsr + ch*4);
    if (tid == 0) sWsr[2400] = Wsr[2400];
    if (tid < C)  sbsr[tid] = bsr[tid];
    cpa_commit();

    {
        const float* gp = x + (size_t)b*C*NN;
        for (int ch = tid; ch < 784; ch += 256) cpa16(planeB[0] + ch*4, gp + ch*4);
        for (int ch = tid; ch < 784; ch += 256){
            int o = ch >> 4, t4 = ch & 15;
            cpa16(wbufB[0] + ch*4, Wq + o*3136 + t4*4);
        }
        cpa_commit();
    }

    u64 acc[7][2];
    #pragma unroll
    for (int t = 0; t < 7; t++){ acc[t][0] = 0ull; acc[t][1] = 0ull; }

    const int ph0 = lane / 7,        pw0 = lane % 7;
    const int ph1 = (lane + 32) / 7, pw1 = (lane + 32) % 7;

    for (int i = 0; i < C; i++){
        if (i + 1 < C){
            const float* gp = x + ((size_t)b*C + (i+1))*NN;
            float* pd = planeB[(i+1)&1];
            float* wd = wbufB [(i+1)&1];
            for (int ch = tid; ch < 784; ch += 256) cpa16(pd + ch*4, gp + ch*4);
            for (int ch = tid; ch < 784; ch += 256){
                int o = ch >> 4, t4 = ch & 15;
                cpa16(wd + ch*4, Wq + o*3136 + (i+1)*64 + t4*4);
            }
            cpa_commit();
            cpa_wait<1>();
        } else {
            cpa_wait<0>();
        }
        __syncthreads();

        const u64* sp2 = (const u64*)planeB[i&1];
        const u64* sw2 = (const u64*)wbufB [i&1];

        #pragma unroll
        for (int kh = 0; kh < 8; kh++){
            u64 pl0[4], pl1[4];
            {
                int base = ((ph0*8 + kh)*28) + pw0*4;
                pl0[0]=sp2[base]; pl0[1]=sp2[base+1]; pl0[2]=sp2[base+2]; pl0[3]=sp2[base+3];
            }
            if (np == 2){
                int base = ((ph1*8 + kh)*28) + pw1*4;
                pl1[0]=sp2[base]; pl1[1]=sp2[base+1]; pl1[2]=sp2[base+2]; pl1[3]=sp2[base+3];
            }
            for (int t = 0; t < no; t++){
                int o = g + 8*t;
                int wbase = o*32 + kh*4;
                u64 w0=sw2[wbase], w1=sw2[wbase+1], w2v=sw2[wbase+2], w3=sw2[wbase+3];
                fma2(acc[t][0], w0, pl0[0]); fma2(acc[t][0], w1,  pl0[1]);
                fma2(acc[t][0], w2v,pl0[2]); fma2(acc[t][0], w3,  pl0[3]);
                if (np == 2){
                    fma2(acc[t][1], w0, pl1[0]); fma2(acc[t][1], w1,  pl1[1]);
                    fma2(acc[t][1], w2v,pl1[2]); fma2(acc[t][1], w3,  pl1[3]);
                }
            }
        }
        __syncthreads();
    }

    for (int t = 0; t < no; t++){
        int o = g + 8*t;
        sq[o*C + lane] = f2lo(acc[t][0]) + f2hi(acc[t][0]);
        if (np == 2)
            sq[o*C + lane + 32] = f2lo(acc[t][1]) + f2hi(acc[t][1]);
    }
    __syncthreads();

    for (int idx = tid; idx < C*C; idx += 256){
        int c = idx / C, i2 = idx % C;
        float s = 0.f;
        #pragma unroll
        for (int j = 0; j < C; j++) s += sq[c*C + j] * sWsr[j*C + i2];
        g_qw[(size_t)b*C*C + idx] = s;
    }
    if (tid < C){
        float s = 0.f;
        #pragma unroll
        for (int j = 0; j < C; j++) s += sq[tid*C + j] * sbsr[j];
        g_qb[b*C + tid] = s;
    }
}

// Fused: v = mean_c x  AND  amax[b,c] = max_n sum_i qw[b,c,i]*x[b,i,n]
__global__ void __launch_bounds__(224) k_amax_v(const float* __restrict__ x){
    __shared__ __align__(16) float xs[C*112];
    __shared__ __align__(16) float qd[C*C*2];
    __shared__ unsigned samax[C];
    const int b = blockIdx.y, n0 = blockIdx.x*112, tid = threadIdx.x;

    for (int idx = tid; idx < C*112; idx += 224){
        int i = idx/112, nn = idx%112;
        xs[idx] = x[((size_t)b*C + i)*NN + n0 + nn];
    }
    for (int idx = tid; idx < C*C; idx += 224){
        float w = g_qw[(size_t)b*C*C + idx];
        qd[2*idx] = w; qd[2*idx+1] = w;
    }
    if (tid < C) samax[tid] = 0u;
    __syncthreads();

    if (tid < 112){
        float s = 0.f;
        #pragma unroll
        for (int i = 0; i < C; i++) s += xs[i*112 + tid];
        g_v[b*NN + n0 + tid] = s * (1.0f/49.0f);
    }

    const int cg = tid / 28, nq = tid % 28;
    u64 acc[7][2];
    #pragma unroll
    for (int t = 0; t < 7; t++){ acc[t][0] = 0ull; acc[t][1] = 0ull; }

    const u64* qd2 = (const u64*)qd;
    const ulonglong2* xs4 = (const ulonglong2*)xs;
    for (int i = 0; i < C; i++){
        ulonglong2 xv = xs4[i*28 + nq];
        #pragma unroll
        for (int t = 0; t < 7; t++){
            int c = cg*7 + t;
            if (c < C){
                u64 w = qd2[c*C + i];
                fma2(acc[t][0], w, xv.x);
                fma2(acc[t][1], w, xv.y);
            }
        }
    }
    #pragma unroll
    for (int t = 0; t < 7; t++){
        int c = cg*7 + t;
        if (c < C){
            float m = fmaxf(fmaxf(f2lo(acc[t][0]), f2hi(acc[t][0])),
                            fmaxf(f2lo(acc[t][1]), f2hi(acc[t][1])));
            atomicMax(&samax[c], fenc(m));
        }
    }
    __syncthreads();
    if (tid < C) atomicMax(&g_amax[b*C + tid], samax[tid]);
}

// s = v @ Wproj^T via 3xTF32 mma.sync. D[b=128 rows, m-tile of 64], K split KS x 448.
// Block 256 thr (8 warps): warp_m = wid>>2 (2 groups of 64 rows), warp_n = wid&3
// (4 groups of 16 cols). Each warp: 4 m16-tiles x 2 n8-tiles. k-chunks of 32,
// double-buffered cp.async. smem pad: stride 36 floats (conflict-free frag loads).
#define SG_PAD 36
__global__ void __launch_bounds__(256) k_sgemm_mma(const float* __restrict__ Wp){
    extern __shared__ __align__(16) float sg[];
    float* va[2] = { sg,               sg + 128*SG_PAD };          // [128][32]
    float* wb[2] = { sg + 2*128*SG_PAD, sg + 2*128*SG_PAD + 64*SG_PAD }; // [64][32]

    const int m0 = blockIdx.x*64;
    const int kb = blockIdx.y*448;
    const int tid = threadIdx.x;
    const int wid = tid >> 5, lane = tid & 31;
    const int warp_m = wid >> 2, warp_n = wid & 3;
    const int lq = lane >> 2, lr = lane & 3;   // group-of-4 id, id-in-group

    float acc[4][2][4];
    #pragma unroll
    for (int mt = 0; mt < 4; mt++)
        #pragma unroll
        for (int nt = 0; nt < 2; nt++)
            #pragma unroll
            for (int r = 0; r < 4; r++) acc[mt][nt][r] = 0.f;

    // prefetch chunk 0
    {
        for (int idx = tid; idx < 1024; idx += 256){
            int row = idx >> 3, q = idx & 7;
            cpa16(va[0] + row*SG_PAD + q*4, g_v + (size_t)row*NN + kb + q*4);
        }
        for (int idx = tid; idx < 512; idx += 256){
            int row = idx >> 3, q = idx & 7;
            cpa16(wb[0] + row*SG_PAD + q*4, Wp + (size_t)(m0+row)*NN + kb + q*4);
        }
        cpa_commit();
    }

    for (int ch = 0; ch < 14; ch++){       // 14 chunks of 32 = 448
        if (ch + 1 < 14){
            int kk0 = (ch+1)*32;
            float* vd = va[(ch+1)&1];
            float* wd = wb[(ch+1)&1];
            for (int idx = tid; idx < 1024; idx += 256){
                int row = idx >> 3, q = idx & 7;
                cpa16(vd + row*SG_PAD + q*4, g_v + (size_t)row*NN + kb + kk0 + q*4);
            }
            for (int idx = tid; idx < 512; idx += 256){
                int row = idx >> 3, q = idx & 7;
                cpa16(wd + row*SG_PAD + q*4, Wp + (size_t)(m0+row)*NN + kb + kk0 + q*4);
            }
            cpa_commit();
            cpa_wait<1>();
        } else {
            cpa_wait<0>();
        }
        __syncthreads();

        const float* vA = va[ch&1];
        const float* wB = wb[ch&1];

        #pragma unroll
        for (int ks8 = 0; ks8 < 4; ks8++){
            const int kk = ks8*8 + lr;
            // B fragments (hi/lo)
            unsigned bh[2][2], bl[2][2];
            #pragma unroll
            for (int nt = 0; nt < 2; nt++){
                int n = warp_n*16 + nt*8 + lq;
                float b0 = wB[n*SG_PAD + kk];
                float b1 = wB[n*SG_PAD + kk + 4];
                tf32_split(b0, bh[nt][0], bl[nt][0]);
                tf32_split(b1, bh[nt][1], bl[nt][1]);
            }
            #pragma unroll
            for (int mt = 0; mt < 4; mt++){
                int r = warp_m*64 + mt*16 + lq;
                float a0 = vA[r*SG_PAD + kk];
                float a1 = vA[(r+8)*SG_PAD + kk];
                float a2 = vA[r*SG_PAD + kk + 4];
                float a3 = vA[(r+8)*SG_PAD + kk + 4];
                unsigned ah[4], al[4];
                tf32_split(a0, ah[0], al[0]);
                tf32_split(a1, ah[1], al[1]);
                tf32_split(a2, ah[2], al[2]);
                tf32_split(a3, ah[3], al[3]);
                #pragma unroll
                for (int nt = 0; nt < 2; nt++){
                    mma_tf32(acc[mt][nt], ah, bh[nt]);
                    mma_tf32(acc[mt][nt], ah, bl[nt]);
                    mma_tf32(acc[mt][nt], al, bh[nt]);
                }
            }
        }
        __syncthreads();
    }

    // epilogue: D[row=batch, col=m] -> g_spart[ksplit][b][m]
    const int pc = blockIdx.y;
    #pragma unroll
    for (int mt = 0; mt < 4; mt++){
        int r = warp_m*64 + mt*16 + lq;
        #pragma unroll
        for (int nt = 0; nt < 2; nt++){
            int m = m0 + warp_n*16 + nt*8 + lr*2;
            float2 s0 = make_float2(acc[mt][nt][0], acc[mt][nt][1]);
            float2 s1 = make_float2(acc[mt][nt][2], acc[mt][nt][3]);
            *(float2*)&g_spart[((size_t)pc*B + r    )*NN + m] = s0;
            *(float2*)&g_spart[((size_t)pc*B + r + 8)*NN + m] = s1;
        }
    }
}

// y[b,m,c] = (amax[b,c]+qb[b,c]) * s[b,m]
__global__ void k_final(float* __restrict__ out){
    __shared__ float ss[64];
    __shared__ float sam[C];
    const int b = blockIdx.y, m0 = blockIdx.x*64, tid = threadIdx.x;
    if (tid < 64){
        float s = 0.f;
        #pragma unroll
        for (int p = 0; p < KS; p++) s += g_spart[((size_t)p*B + b)*NN + m0 + tid];
        ss[tid] = s;
    }
    if (tid >= 64 && tid < 64 + C){
        int c = tid - 64;
        sam[c] = fdec(g_amax[b*C + c]) + g_qb[b*C + c];
    }
    __syncthreads();
    float* ob = out + ((size_t)b*NN + m0)*C;
    for (int idx = tid; idx < 64*C; idx += 256){
        int mi = idx / C, c = idx % C;
        ob[idx] = sam[c] * ss[mi];
    }
}

// ---------------- launch ----------------
extern "C" void kernel_launch(void* const* d_in, const int* in_sizes, int n_in,
                              void* d_out, int out_size){
    const float* x    = (const float*)d_in[0];
    const float* Wq   = (const float*)d_in[1];
    const float* Wsr  = (const float*)d_in[2];
    const float* bsr  = (const float*)d_in[3];
    const float* Wp   = (const float*)d_in[4];
    float* out = (float*)d_out;

    const int qsmem = 14994 * 4;
    const int gsmem = (2*128*SG_PAD + 2*64*SG_PAD) * 4;   // 55296 B
    cudaFuncSetAttribute(k_qconv_qw, cudaFuncAttributeMaxDynamicSharedMemorySize, qsmem);
    cudaFuncSetAttribute(k_sgemm_mma, cudaFuncAttributeMaxDynamicSharedMemorySize, gsmem);

    k_init      <<< (B*C + 255)/256, 256 >>> ();
    k_qconv_qw  <<< B, 256, qsmem >>> (x, Wq, Wsr, bsr);
    k_amax_v    <<< dim3(28, B), 224 >>> (x);
    k_sgemm_mma <<< dim3(49, KS), 256, gsmem >>> (Wp);
    k_final     <<< dim3(49, B), 256 >>> (out);
}

// round 14
// speedup vs baseline: 2.0029x; 1.3285x over previous
#include <cuda_runtime.h>

#define B  128
#define C  49
#define NN 3136   // tokens = 56*56
#define KS 7      // k-splits for s-gemm (3136 = 7*448)

typedef unsigned long long u64;

// ---------------- scratch (device globals; no allocation) ----------------
__device__ float    g_v[B*NN];
__device__ float    g_qw[B*C*C];
__device__ float    g_qb[B*C];
__device__ unsigned g_amax[B*C];
__device__ float    g_spart[KS*B*NN];

// ---------------- helpers ----------------
__device__ __forceinline__ void fma2(u64 &d, u64 a, u64 b) {
    asm("fma.rn.f32x2 %0, %1, %2, %0;" : "+l"(d) : "l"(a), "l"(b));
}
__device__ __forceinline__ float f2lo(u64 v){ return __uint_as_float((unsigned)v); }
__device__ __forceinline__ float f2hi(u64 v){ return __uint_as_float((unsigned)(v>>32)); }

__device__ __forceinline__ unsigned fenc(float f){
    unsigned u = __float_as_uint(f);
    return (u & 0x80000000u) ? ~u : (u | 0x80000000u);
}
__device__ __forceinline__ float fdec(unsigned e){
    return (e & 0x80000000u) ? __uint_as_float(e & 0x7FFFFFFFu)
                             : __uint_as_float(~e);
}

__device__ __forceinline__ void cpa16(float* s, const float* g){
    unsigned ss = (unsigned)__cvta_generic_to_shared(s);
    asm volatile("cp.async.cg.shared.global [%0], [%1], 16;" :: "r"(ss), "l"(g));
}
__device__ __forceinline__ void cpa_commit(){
    asm volatile("cp.async.commit_group;");
}
template<int N>
__device__ __forceinline__ void cpa_wait(){
    asm volatile("cp.async.wait_group %0;" :: "n"(N));
}

// tf32 split helpers
__device__ __forceinline__ unsigned tf32_of(float x){
    unsigned r; asm("cvt.rna.tf32.f32 %0, %1;" : "=r"(r) : "f"(x)); return r;
}
__device__ __forceinline__ void tf32_split(float x, unsigned &hi, unsigned &lo){
    hi = tf32_of(x);
    lo = tf32_of(x - __uint_as_float(hi));
}
__device__ __forceinline__ void mma_tf32(float* d, const unsigned* a, const unsigned* b){
    asm("mma.sync.aligned.m16n8k8.row.col.f32.tf32.tf32.f32 "
        "{%0,%1,%2,%3}, {%4,%5,%6,%7}, {%8,%9}, {%0,%1,%2,%3};"
        : "+f"(d[0]), "+f"(d[1]), "+f"(d[2]), "+f"(d[3])
        : "r"(a[0]), "r"(a[1]), "r"(a[2]), "r"(a[3]), "r"(b[0]), "r"(b[1]));
}

// ---------------- kernels ----------------

__global__ void k_init(){
    int i = blockIdx.x*256 + threadIdx.x;
    if (i < B*C) g_amax[i] = 0u;
}

// Fused: q = Conv2d(x,Wq,8,str8) -> qw = q@Wsr, qb = q@bsr.
// 512 threads: warps 0-7 reduce i in [0,25), warps 8-15 reduce i in [25,49).
__global__ void __launch_bounds__(512) k_qconv_qw(const float* __restrict__ x,
                                                  const float* __restrict__ Wq,
                                                  const float* __restrict__ Wsr,
                                                  const float* __restrict__ bsr){
    extern __shared__ __align__(16) float smem[];
    float* sWsr = smem + 8*3136;
    float* sbsr = sWsr + 2401;
    float* sq   = smem;                  // epilogue reuse

    const int b = blockIdx.x, tid = threadIdx.x;
    const int wid = tid >> 5, lane = tid & 31;
    const int half = wid >> 3;           // 0: i in [0,25), 1: i in [25,49)
    const int g = wid & 7;
    const int no = (g == 0) ? 7 : 6;     // o = g + 8*t
    const int np = (lane < 17) ? 2 : 1;  // p = lane (+32)

    for (int ch = tid; ch < 600; ch += 512) cpa16(sWsr + ch*4, Wsr + ch*4);
    if (tid == 0) sWsr[2400] = Wsr[2400];
    if (tid < C)  sbsr[tid] = bsr[tid];
    cpa_commit();

    {
        for (int h = 0; h < 2; h++){
            int i = h*25;
            const float* gp = x + ((size_t)b*C + i)*NN;
            float* pd = smem + (h*2 + 0)*3136;
            float* wd = smem + (4 + h*2 + 0)*3136;
            for (int ch = tid; ch < 784; ch += 512) cpa16(pd + ch*4, gp + ch*4);
            for (int ch = tid; ch < 784; ch += 512){
                int o = ch >> 4, t4 = ch & 15;
                cpa16(wd + ch*4, Wq + o*3136 + i*64 + t4*4);
            }
        }
        cpa_commit();
    }

    u64 acc[7][2];
    #pragma unroll
    for (int t = 0; t < 7; t++){ acc[t][0] = 0ull; acc[t][1] = 0ull; }

    const int ph0 = lane / 7,        pw0 = lane % 7;
    const int ph1 = (lane + 32) / 7, pw1 = (lane + 32) % 7;

    for (int it = 0; it < 25; it++){
        if (it + 1 < 25){
            int par = (it+1)&1;
            for (int h = 0; h < 2; h++){
                int i = h*25 + it + 1;
                if (i >= C) break;
                const float* gp = x + ((size_t)b*C + i)*NN;
                float* pd = smem + (h*2 + par)*3136;
                float* wd = smem + (4 + h*2 + par)*3136;
                for (int ch = tid; ch < 784; ch += 512) cpa16(pd + ch*4, gp + ch*4);
                for (int ch = tid; ch < 784; ch += 512){
                    int o = ch >> 4, t4 = ch & 15;
                    cpa16(wd + ch*4, Wq + o*3136 + i*64 + t4*4);
                }
            }
            cpa_commit();
            cpa_wait<1>();
        } else {
            cpa_wait<0>();
        }
        __syncthreads();

        const int myi = half*25 + it;
        if (myi < C){
            const int par = it & 1;
            const u64* sp2 = (const u64*)(smem + (half*2 + par)*3136);
            const u64* sw2 = (const u64*)(smem + (4 + half*2 + par)*3136);

            #pragma unroll
            for (int kh = 0; kh < 8; kh++){
                u64 pl0[4], pl1[4];
                {
                    int base = ((ph0*8 + kh)*28) + pw0*4;
                    pl0[0]=sp2[base]; pl0[1]=sp2[base+1]; pl0[2]=sp2[base+2]; pl0[3]=sp2[base+3];
                }
                if (np == 2){
                    int base = ((ph1*8 + kh)*28) + pw1*4;
                    pl1[0]=sp2[base]; pl1[1]=sp2[base+1]; pl1[2]=sp2[base+2]; pl1[3]=sp2[base+3];
                }
                for (int t = 0; t < no; t++){
                    int o = g + 8*t;
                    int wbase = o*32 + kh*4;
                    u64 w0=sw2[wbase], w1=sw2[wbase+1], w2v=sw2[wbase+2], w3=sw2[wbase+3];
                    fma2(acc[t][0], w0, pl0[0]); fma2(acc[t][0], w1,  pl0[1]);
                    fma2(acc[t][0], w2v,pl0[2]); fma2(acc[t][0], w3,  pl0[3]);
                    if (np == 2){
                        fma2(acc[t][1], w0, pl1[0]); fma2(acc[t][1], w1,  pl1[1]);
                        fma2(acc[t][1], w2v,pl1[2]); fma2(acc[t][1], w3,  pl1[3]);
                    }
                }
            }
        }
        __syncthreads();
    }

    if (half == 0){
        for (int t = 0; t < no; t++){
            int o = g + 8*t;
            sq[o*C + lane] = f2lo(acc[t][0]) + f2hi(acc[t][0]);
            if (np == 2)
                sq[o*C + lane + 32] = f2lo(acc[t][1]) + f2hi(acc[t][1]);
        }
    }
    __syncthreads();
    if (half == 1){
        for (int t = 0; t < no; t++){
            int o = g + 8*t;
            sq[o*C + lane] += f2lo(acc[t][0]) + f2hi(acc[t][0]);
            if (np == 2)
                sq[o*C + lane + 32] += f2lo(acc[t][1]) + f2hi(acc[t][1]);
        }
    }
    __syncthreads();

    for (int idx = tid; idx < C*C; idx += 512){
        int c = idx / C, i2 = idx % C;
        float s = 0.f;
        #pragma unroll
        for (int j = 0; j < C; j++) s += sq[c*C + j] * sWsr[j*C + i2];
        g_qw[(size_t)b*C*C + idx] = s;
    }
    if (tid < C){
        float s = 0.f;
        #pragma unroll
        for (int j = 0; j < C; j++) s += sq[tid*C + j] * sbsr[j];
        g_qb[b*C + tid] = s;
    }
}

// Fused: v = mean_c x AND amax[b,c] = max_n sum_i qw[b,c,i]*x[b,i,n]
// Re-tiled: n-tile 224 (NB=8/thread), c = cg + 8*t (all 8 groups active),
// weight loaded once per (c,i) and reused across 8 n-values.
__global__ void __launch_bounds__(224) k_amax_v(const float* __restrict__ x){
    extern __shared__ __align__(16) float asm_[];
    float* xs = asm_;                       // [C][224]
    float* qd = asm_ + C*224;               // [C][C] duplicated pairs
    unsigned* samax = (unsigned*)(qd + C*C*2);
    const int b = blockIdx.y, n0 = blockIdx.x*224, tid = threadIdx.x;

    for (int i = 0; i < C; i++)
        xs[i*224 + tid] = x[((size_t)b*C + i)*NN + n0 + tid];
    for (int idx = tid; idx < C*C; idx += 224){
        float w = g_qw[(size_t)b*C*C + idx];
        qd[2*idx] = w; qd[2*idx+1] = w;
    }
    if (tid < C) samax[tid] = 0u;
    __syncthreads();

    // channel mean -> v (i ascending: same order as before)
    {
        float s = 0.f;
        #pragma unroll
        for (int i = 0; i < C; i++) s += xs[i*224 + tid];
        g_v[b*NN + n0 + tid] = s * (1.0f/49.0f);
    }

    const int cg = tid / 28, nq = tid % 28;   // c = cg + 8*t
    u64 acc[7][4];
    #pragma unroll
    for (int t = 0; t < 7; t++)
        #pragma unroll
        for (int j = 0; j < 4; j++) acc[t][j] = 0ull;

    const u64* qd2 = (const u64*)qd;
    const ulonglong2* xs4 = (const ulonglong2*)xs;
    for (int i = 0; i < C; i++){
        ulonglong2 xv0 = xs4[i*56 + nq*2];
        ulonglong2 xv1 = xs4[i*56 + nq*2 + 1];
        #pragma unroll
        for (int t = 0; t < 7; t++){
            int c = cg + 8*t;
            if (c < C){
                u64 w = qd2[c*C + i];
                fma2(acc[t][0], w, xv0.x);
                fma2(acc[t][1], w, xv0.y);
                fma2(acc[t][2], w, xv1.x);
                fma2(acc[t][3], w, xv1.y);
            }
        }
    }
    #pragma unroll
    for (int t = 0; t < 7; t++){
        int c = cg + 8*t;
        if (c < C){
            float m0 = fmaxf(fmaxf(f2lo(acc[t][0]), f2hi(acc[t][0])),
                             fmaxf(f2lo(acc[t][1]), f2hi(acc[t][1])));
            float m1 = fmaxf(fmaxf(f2lo(acc[t][2]), f2hi(acc[t][2])),
                             fmaxf(f2lo(acc[t][3]), f2hi(acc[t][3])));
            atomicMax(&samax[c], fenc(fmaxf(m0, m1)));
        }
    }
    __syncthreads();
    if (tid < C) atomicMax(&g_amax[b*C + tid], samax[tid]);
}

// s = v @ Wproj^T via 3xTF32 mma.sync (unchanged from R6)
#define SG_PAD 36
__global__ void __launch_bounds__(256) k_sgemm_mma(const float* __restrict__ Wp){
    extern __shared__ __align__(16) float sg[];
    float* va[2] = { sg,               sg + 128*SG_PAD };
    float* wb[2] = { sg + 2*128*SG_PAD, sg + 2*128*SG_PAD + 64*SG_PAD };

    const int m0 = blockIdx.x*64;
    const int kb = blockIdx.y*448;
    const int tid = threadIdx.x;
    const int wid = tid >> 5, lane = tid & 31;
    const int warp_m = wid >> 2, warp_n = wid & 3;
    const int lq = lane >> 2, lr = lane & 3;

    float acc[4][2][4];
    #pragma unroll
    for (int mt = 0; mt < 4; mt++)
        #pragma unroll
        for (int nt = 0; nt < 2; nt++)
            #pragma unroll
            for (int r = 0; r < 4; r++) acc[mt][nt][r] = 0.f;

    {
        for (int idx = tid; idx < 1024; idx += 256){
            int row = idx >> 3, q = idx & 7;
            cpa16(va[0] + row*SG_PAD + q*4, g_v + (size_t)row*NN + kb + q*4);
        }
        for (int idx = tid; idx < 512; idx += 256){
            int row = idx >> 3, q = idx & 7;
            cpa16(wb[0] + row*SG_PAD + q*4, Wp + (size_t)(m0+row)*NN + kb + q*4);
        }
        cpa_commit();
    }

    for (int ch = 0; ch < 14; ch++){
        if (ch + 1 < 14){
            int kk0 = (ch+1)*32;
            float* vd = va[(ch+1)&1];
            float* wd = wb[(ch+1)&1];
            for (int idx = tid; idx < 1024; idx += 256){
                int row = idx >> 3, q = idx & 7;
                cpa16(vd + row*SG_PAD + q*4, g_v + (size_t)row*NN + kb + kk0 + q*4);
            }
            for (int idx = tid; idx < 512; idx += 256){
                int row = idx >> 3, q = idx & 7;
                cpa16(wd + row*SG_PAD + q*4, Wp + (size_t)(m0+row)*NN + kb + kk0 + q*4);
            }
            cpa_commit();
            cpa_wait<1>();
        } else {
            cpa_wait<0>();
        }
        __syncthreads();

        const float* vA = va[ch&1];
        const float* wB = wb[ch&1];

        #pragma unroll
        for (int ks8 = 0; ks8 < 4; ks8++){
            const int kk = ks8*8 + lr;
            unsigned bh[2][2], bl[2][2];
            #pragma unroll
            for (int nt = 0; nt < 2; nt++){
                int n = warp_n*16 + nt*8 + lq;
                float b0 = wB[n*SG_PAD + kk];
                float b1 = wB[n*SG_PAD + kk + 4];
                tf32_split(b0, bh[nt][0], bl[nt][0]);
                tf32_split(b1, bh[nt][1], bl[nt][1]);
            }
            #pragma unroll
            for (int mt = 0; mt < 4; mt++){
                int r = warp_m*64 + mt*16 + lq;
                float a0 = vA[r*SG_PAD + kk];
                float a1 = vA[(r+8)*SG_PAD + kk];
                float a2 = vA[r*SG_PAD + kk + 4];
                float a3 = vA[(r+8)*SG_PAD + kk + 4];
                unsigned ah[4], al[4];
                tf32_split(a0, ah[0], al[0]);
                tf32_split(a1, ah[1], al[1]);
                tf32_split(a2, ah[2], al[2]);
                tf32_split(a3, ah[3], al[3]);
                #pragma unroll
                for (int nt = 0; nt < 2; nt++){
                    mma_tf32(acc[mt][nt], ah, bh[nt]);
                    mma_tf32(acc[mt][nt], ah, bl[nt]);
                    mma_tf32(acc[mt][nt], al, bh[nt]);
                }
            }
        }
        __syncthreads();
    }

    const int pc = blockIdx.y;
    #pragma unroll
    for (int mt = 0; mt < 4; mt++){
        int r = warp_m*64 + mt*16 + lq;
        #pragma unroll
        for (int nt = 0; nt < 2; nt++){
            int m = m0 + warp_n*16 + nt*8 + lr*2;
            float2 s0 = make_float2(acc[mt][nt][0], acc[mt][nt][1]);
            float2 s1 = make_float2(acc[mt][nt][2], acc[mt][nt][3]);
            *(float2*)&g_spart[((size_t)pc*B + r    )*NN + m] = s0;
            *(float2*)&g_spart[((size_t)pc*B + r + 8)*NN + m] = s1;
        }
    }
}

// y[b,m,c] = (amax[b,c]+qb[b,c]) * s[b,m]
__global__ void k_final(float* __restrict__ out){
    __shared__ float ss[64];
    __shared__ float sam[C];
    const int b = blockIdx.y, m0 = blockIdx.x*64, tid = threadIdx.x;
    if (tid < 64){
        float s = 0.f;
        #pragma unroll
        for (int p = 0; p < KS; p++) s += g_spart[((size_t)p*B + b)*NN + m0 + tid];
        ss[tid] = s;
    }
    if (tid >= 64 && tid < 64 + C){
        int c = tid - 64;
        sam[c] = fdec(g_amax[b*C + c]) + g_qb[b*C + c];
    }
    __syncthreads();
    float* ob = out + ((size_t)b*NN + m0)*C;
    for (int idx = tid; idx < 64*C; idx += 256){
        int mi = idx / C, c = idx % C;
        ob[idx] = sam[c] * ss[mi];
    }
}

// ---------------- launch ----------------
extern "C" void kernel_launch(void* const* d_in, const int* in_sizes, int n_in,
                              void* d_out, int out_size){
    const float* x    = (const float*)d_in[0];
    const float* Wq   = (const float*)d_in[1];
    const float* Wsr  = (const float*)d_in[2];
    const float* bsr  = (const float*)d_in[3];
    const float* Wp   = (const float*)d_in[4];
    float* out = (float*)d_out;

    const int qsmem = (8*3136 + 2401 + 49 + 32) * 4;        // ~110.3 KB
    const int asmem = (C*224 + C*C*2) * 4 + C * 4 + 16;     // ~63.3 KB
    const int gsmem = (2*128*SG_PAD + 2*64*SG_PAD) * 4;     // 55296 B
    cudaFuncSetAttribute(k_qconv_qw, cudaFuncAttributeMaxDynamicSharedMemorySize, qsmem);
    cudaFuncSetAttribute(k_amax_v,   cudaFuncAttributeMaxDynamicSharedMemorySize, asmem);
    cudaFuncSetAttribute(k_sgemm_mma, cudaFuncAttributeMaxDynamicSharedMemorySize, gsmem);

    k_init      <<< (B*C + 255)/256, 256 >>> ();
    k_qconv_qw  <<< B, 512, qsmem >>> (x, Wq, Wsr, bsr);
    k_amax_v    <<< dim3(14, B), 224, asmem >>> (x);
    k_sgemm_mma <<< dim3(49, KS), 256, gsmem >>> (Wp);
    k_final     <<< dim3(49, B), 256 >>> (out);
}